// round 7
// baseline (speedup 1.0000x reference)
#include <cuda_runtime.h>

#define N_NODES 100000
#define N_EDGES 1600000
#define D 64

// Scratch (device globals — no allocation allowed in kernel_launch)
__device__ __align__(16) float g_accum[N_NODES * D];  // 25.6 MB weighted sums per dst
__device__ float g_deg[N_NODES];                      // in-degree per dst

// ---------------------------------------------------------------------------
// Kernel 1: zero the accumulators (graph replays reuse the globals)
// ---------------------------------------------------------------------------
__global__ void zero_kernel() {
    int i = blockIdx.x * blockDim.x + threadIdx.x;
    float4* a = reinterpret_cast<float4*>(g_accum);
    const int n4 = (N_NODES * D) / 4;   // 1.6M float4
    if (i < n4) a[i] = make_float4(0.f, 0.f, 0.f, 0.f);
    if (i < N_NODES) g_deg[i] = 0.f;
}

// ---------------------------------------------------------------------------
// Kernel 2: edge scatter. 8 threads per edge, each handles 8 floats
// (2x float4 gather + 2x red.global.add.v4.f32). Degree counted by lane 0.
// NOTE: src/dst are int32 (JAX x64 disabled -> jnp.int64 request yields int32).
// ---------------------------------------------------------------------------
__global__ void edge_kernel(const float4* __restrict__ featv,
                            const int* __restrict__ src,
                            const int* __restrict__ dst,
                            const float* __restrict__ ew) {
    int t = blockIdx.x * blockDim.x + threadIdx.x;
    int e = t >> 3;
    if (e >= N_EDGES) return;
    int p = t & 7;

    int   s = __ldg(src + e);
    int   d = __ldg(dst + e);
    float w = __ldg(ew + e);

    float4 f0 = __ldg(featv + (size_t)s * 16 + p * 2);
    float4 f1 = __ldg(featv + (size_t)s * 16 + p * 2 + 1);

    float* base = g_accum + (size_t)d * D + p * 8;
    asm volatile("red.global.add.v4.f32 [%0], {%1, %2, %3, %4};"
                 :: "l"(base), "f"(f0.x * w), "f"(f0.y * w), "f"(f0.z * w), "f"(f0.w * w)
                 : "memory");
    asm volatile("red.global.add.v4.f32 [%0], {%1, %2, %3, %4};"
                 :: "l"(base + 4), "f"(f1.x * w), "f"(f1.y * w), "f"(f1.z * w), "f"(f1.w * w)
                 : "memory");
    if (p == 0) {
        atomicAdd(g_deg + d, 1.0f);
    }
}

// ---------------------------------------------------------------------------
// Kernel 3: per-node mean + dual GEMV + bias.
// Block = 256 threads = 16 nodes/tile, 16 threads per node, 4 outputs each.
// Weights staged in shared, k-major float4 layout:
//   sW[kq*64 + j] = float4(W[j][4kq .. 4kq+3])
// Thread (node, jq) computes outputs j = jj*16 + jq  (jj = 0..3), so the 16
// lanes of one node read 16 CONSECUTIVE float4s -> conflict-free LDS.128.
// ---------------------------------------------------------------------------
__global__ void node_kernel(const float4* __restrict__ featv,
                            const float* __restrict__ W_neigh,
                            const float* __restrict__ W_self,
                            const float* __restrict__ bias,
                            float* __restrict__ out) {
    __shared__ float4 sWs[16 * 64];   // W_self,  16 KB
    __shared__ float4 sWn[16 * 64];   // W_neigh, 16 KB

    // Stage weights (transposed to k-major quads)
    for (int i = threadIdx.x; i < 16 * 64; i += blockDim.x) {
        int j  = i & 63;
        int kq = i >> 6;
        sWs[i] = reinterpret_cast<const float4*>(W_self )[j * 16 + kq];
        sWn[i] = reinterpret_cast<const float4*>(W_neigh)[j * 16 + kq];
    }
    __syncthreads();

    const int jq = threadIdx.x & 15;
    const float4* accv = reinterpret_cast<const float4*>(g_accum);

    for (int base = blockIdx.x * 16; base < N_NODES; base += gridDim.x * 16) {
        int node = base + (threadIdx.x >> 4);
        if (node >= N_NODES) continue;

        float invd = 1.0f / fmaxf(g_deg[node], 1.0f);
        const float4* fv = featv + (size_t)node * 16;
        const float4* av = accv + (size_t)node * 16;

        float acc0 = 0.f, acc1 = 0.f, acc2 = 0.f, acc3 = 0.f;

        #pragma unroll
        for (int kq = 0; kq < 16; ++kq) {
            float4 f  = __ldg(fv + kq);
            float4 nb = av[kq];
            nb.x *= invd; nb.y *= invd; nb.z *= invd; nb.w *= invd;

            float4 ws, wn;
            ws = sWs[kq * 64 + 0 * 16 + jq];
            wn = sWn[kq * 64 + 0 * 16 + jq];
            acc0 += f.x * ws.x + f.y * ws.y + f.z * ws.z + f.w * ws.w
                  + nb.x * wn.x + nb.y * wn.y + nb.z * wn.z + nb.w * wn.w;
            ws = sWs[kq * 64 + 1 * 16 + jq];
            wn = sWn[kq * 64 + 1 * 16 + jq];
            acc1 += f.x * ws.x + f.y * ws.y + f.z * ws.z + f.w * ws.w
                  + nb.x * wn.x + nb.y * wn.y + nb.z * wn.z + nb.w * wn.w;
            ws = sWs[kq * 64 + 2 * 16 + jq];
            wn = sWn[kq * 64 + 2 * 16 + jq];
            acc2 += f.x * ws.x + f.y * ws.y + f.z * ws.z + f.w * ws.w
                  + nb.x * wn.x + nb.y * wn.y + nb.z * wn.z + nb.w * wn.w;
            ws = sWs[kq * 64 + 3 * 16 + jq];
            wn = sWn[kq * 64 + 3 * 16 + jq];
            acc3 += f.x * ws.x + f.y * ws.y + f.z * ws.z + f.w * ws.w
                  + nb.x * wn.x + nb.y * wn.y + nb.z * wn.z + nb.w * wn.w;
        }

        float* o = out + (size_t)node * D;
        o[0 * 16 + jq] = acc0 + __ldg(bias + 0 * 16 + jq);
        o[1 * 16 + jq] = acc1 + __ldg(bias + 1 * 16 + jq);
        o[2 * 16 + jq] = acc2 + __ldg(bias + 2 * 16 + jq);
        o[3 * 16 + jq] = acc3 + __ldg(bias + 3 * 16 + jq);
    }
}

// ---------------------------------------------------------------------------
extern "C" void kernel_launch(void* const* d_in, const int* in_sizes, int n_in,
                              void* d_out, int out_size) {
    const float* feat = (const float*)d_in[0];
    const int*   src  = (const int*)d_in[1];    // int32 (JAX x64 disabled)
    const int*   dst  = (const int*)d_in[2];
    const float* ew   = (const float*)d_in[3];
    const float* Wn   = (const float*)d_in[4];
    const float* Ws   = (const float*)d_in[5];
    const float* bias = (const float*)d_in[6];
    float*       out  = (float*)d_out;

    // Zero accumulators: 1.6M float4 -> 6250 blocks x 256
    zero_kernel<<<6250, 256>>>();

    // Edge scatter: 1.6M edges x 8 threads = 12.8M threads
    edge_kernel<<<(N_EDGES * 8 + 255) / 256, 256>>>(
        (const float4*)feat, src, dst, ew);

    // Node transform: 16 nodes per block-tile
    node_kernel<<<1480, 256>>>((const float4*)feat, Wn, Ws, bias, out);
}